// round 1
// baseline (speedup 1.0000x reference)
#include <cuda_runtime.h>
#include <math.h>

#define NB    32
#define EDIM  256
#define NHEAD 8
#define KDIM  16
#define VDIM  64
#define DHD   512
#define HQ    768
#define NPIX  400
#define SPIX  196
#define PADV  66

// ---------------- device scratch (static, no allocation) ----------------
__device__ float g_qkv [NB*HQ*NPIX];        // qkv conv output   [b][768][400]
__device__ float g_qdw [NB*128*NPIX];       // dwconv(q)         [b][128][400]
__device__ float g_tmpb[NHEAD*NPIX*SPIX];   // bias stage 1      [h][400][196]
__device__ float g_bias[NHEAD*NPIX*NPIX];   // full bias         [h][400][400]
__device__ float g_ot  [NB*NPIX*DHD];       // attention out, transposed [b][400][512]
__device__ float g_y1  [NB*EDIM*NPIX];      // x + proj          [b][256][400]
__device__ float g_hb  [NB*DHD*NPIX];       // relu(pw1)         [b][512][400]
__device__ int   g_midx[NPIX*4];            // bicubic tap indices
__device__ float g_mw  [NPIX*4];            // bicubic tap weights

// ---------------- bicubic interpolation taps (M is 4-sparse per row) ----
__global__ void k_mtaps() {
    int i = blockIdx.x*blockDim.x + threadIdx.x;
    if (i >= NPIX) return;
    double scale = (double)SPIX / (double)NPIX;
    double src = (i + 0.5)*scale - 0.5;
    double f = floor(src);
    double t = src - f;
    const double a = -0.75;
    for (int j = -1; j <= 2; j++) {
        double xx = fabs((double)j - t);
        double w;
        if (xx <= 1.0)      w = (a+2.0)*xx*xx*xx - (a+3.0)*xx*xx + 1.0;
        else if (xx < 2.0)  w = a*xx*xx*xx - 5.0*a*xx*xx + 8.0*a*xx - 4.0*a;
        else                w = 0.0;
        int idx = (int)f + j;
        idx = min(max(idx, 0), SPIX-1);
        g_midx[i*4 + (j+1)] = idx;
        g_mw  [i*4 + (j+1)] = (float)w;
    }
}

// tmp[h][n][t] = sum_k w[n,k] * ab[h, idxs[midx[n,k], t]]
__global__ void k_bias1(const float* __restrict__ ab, const int* __restrict__ idxs) {
    int i = blockIdx.x*blockDim.x + threadIdx.x;
    if (i >= NHEAD*NPIX*SPIX) return;
    int t = i % SPIX;
    int n = (i / SPIX) % NPIX;
    int h = i / (SPIX*NPIX);
    float acc = 0.f;
    #pragma unroll
    for (int k = 0; k < 4; k++) {
        int s = g_midx[n*4+k];
        acc += g_mw[n*4+k] * ab[h*SPIX + idxs[s*SPIX + t]];
    }
    g_tmpb[i] = acc;
}

// bias[h][n][m] = sum_k w[m,k] * tmp[h][n][midx[m,k]]
__global__ void k_bias2() {
    int i = blockIdx.x*blockDim.x + threadIdx.x;
    if (i >= NHEAD*NPIX*NPIX) return;
    int m = i % NPIX;
    int n = (i / NPIX) % NPIX;
    int h = i / (NPIX*NPIX);
    const float* trow = g_tmpb + ((size_t)h*NPIX + n)*SPIX;
    float acc = 0.f;
    #pragma unroll
    for (int k = 0; k < 4; k++)
        acc += g_mw[m*4+k] * trow[g_midx[m*4+k]];
    g_bias[i] = acc;
}

// ---------------- depthwise 3x3 on q channels (128 ch, 20x20, SAME) ----
__global__ void k_dwconv(const float* __restrict__ w, const float* __restrict__ s,
                         const float* __restrict__ bia) {
    int i = blockIdx.x*blockDim.x + threadIdx.x;
    if (i >= NB*128*NPIX) return;
    int p = i % NPIX;
    int c = (i / NPIX) % 128;
    int b = i / (128*NPIX);
    int y = p / 20, x = p % 20;
    const float* src = g_qkv + ((size_t)b*HQ + c)*NPIX;
    float acc = 0.f;
    #pragma unroll
    for (int dy = -1; dy <= 1; dy++) {
        int yy = y + dy;
        if (yy < 0 || yy >= 20) continue;
        #pragma unroll
        for (int dx = -1; dx <= 1; dx++) {
            int xx = x + dx;
            if (xx < 0 || xx >= 20) continue;
            acc += w[c*9 + (dy+1)*3 + (dx+1)] * src[yy*20 + xx];
        }
    }
    g_qdw[i] = acc * s[c] + bia[c];
}

// ---------------- generic conv1x1 GEMM ----------------
// Y[b,o,p] = act_out( sc[o] * sum_ci W[o,ci]*act_in(X[b,ci,p]) + bi[o] ) (+R[b,o,p])
// flags: bit0 reluIn, bit1 reluOut, bit2 X is transposed [b][p][Cin]
__global__ void __launch_bounds__(256) k_gemm(
    const float* __restrict__ X, const float* __restrict__ W,
    const float* __restrict__ sc, const float* __restrict__ bi,
    const float* __restrict__ R, float* __restrict__ Y,
    int O, int Cin, int flags)
{
    __shared__ float Ws[16][64];
    __shared__ float Xs[16][64];
    const int b  = blockIdx.z;
    const int oT = blockIdx.y * 64;
    const int pT = blockIdx.x * 64;
    const int t  = threadIdx.x;
    const int ty = t >> 4, tx = t & 15;
    const bool reluIn = flags & 1;
    const bool xT     = flags & 4;

    float acc[4][4];
    #pragma unroll
    for (int i = 0; i < 4; i++)
        #pragma unroll
        for (int j = 0; j < 4; j++) acc[i][j] = 0.f;

    const int mW = t >> 2;
    const int kW = (t & 3) * 4;

    for (int k0 = 0; k0 < Cin; k0 += 16) {
        // W tile: coalesced over ci
        float4 wv = *(const float4*)&W[(size_t)(oT + mW)*Cin + k0 + kW];
        Ws[kW+0][mW] = wv.x; Ws[kW+1][mW] = wv.y;
        Ws[kW+2][mW] = wv.z; Ws[kW+3][mW] = wv.w;
        // X tile
        if (!xT) {
            const int kx = t >> 4;
            const int px = (t & 15) * 4;
            const int p  = pT + px;
            float4 xv = make_float4(0.f, 0.f, 0.f, 0.f);
            if (p < NPIX)
                xv = *(const float4*)&X[((size_t)b*Cin + k0 + kx)*NPIX + p];
            if (reluIn) {
                xv.x = fmaxf(xv.x, 0.f); xv.y = fmaxf(xv.y, 0.f);
                xv.z = fmaxf(xv.z, 0.f); xv.w = fmaxf(xv.w, 0.f);
            }
            Xs[kx][px+0] = xv.x; Xs[kx][px+1] = xv.y;
            Xs[kx][px+2] = xv.z; Xs[kx][px+3] = xv.w;
        } else {
            const int px = t >> 2;
            const int kx = (t & 3) * 4;
            const int p  = pT + px;
            float4 xv = make_float4(0.f, 0.f, 0.f, 0.f);
            if (p < NPIX)
                xv = *(const float4*)&X[((size_t)b*NPIX + p)*Cin + k0 + kx];
            if (reluIn) {
                xv.x = fmaxf(xv.x, 0.f); xv.y = fmaxf(xv.y, 0.f);
                xv.z = fmaxf(xv.z, 0.f); xv.w = fmaxf(xv.w, 0.f);
            }
            Xs[kx+0][px] = xv.x; Xs[kx+1][px] = xv.y;
            Xs[kx+2][px] = xv.z; Xs[kx+3][px] = xv.w;
        }
        __syncthreads();
        #pragma unroll
        for (int k = 0; k < 16; k++) {
            float4 av = *(const float4*)&Ws[k][ty*4];
            float4 bv = *(const float4*)&Xs[k][tx*4];
            acc[0][0] += av.x*bv.x; acc[0][1] += av.x*bv.y; acc[0][2] += av.x*bv.z; acc[0][3] += av.x*bv.w;
            acc[1][0] += av.y*bv.x; acc[1][1] += av.y*bv.y; acc[1][2] += av.y*bv.z; acc[1][3] += av.y*bv.w;
            acc[2][0] += av.z*bv.x; acc[2][1] += av.z*bv.y; acc[2][2] += av.z*bv.z; acc[2][3] += av.z*bv.w;
            acc[3][0] += av.w*bv.x; acc[3][1] += av.w*bv.y; acc[3][2] += av.w*bv.z; acc[3][3] += av.w*bv.w;
        }
        __syncthreads();
    }

    const bool reluOut = flags & 2;
    #pragma unroll
    for (int i = 0; i < 4; i++) {
        const int o = oT + ty*4 + i;
        const float s  = sc[o];
        const float bb = bi[o];
        #pragma unroll
        for (int j = 0; j < 4; j++) {
            const int p = pT + tx*4 + j;
            if (p < NPIX) {
                float y = acc[i][j]*s + bb;
                if (reluOut) y = fmaxf(y, 0.f);
                const size_t off = ((size_t)b*O + o)*NPIX + p;
                if (R) y += R[off];
                Y[off] = y;
            }
        }
    }
}

// ---------------- fused attention: one CTA per (b,h) ----------------
// K,V,Q for this (b,h) fit in smem. Each warp owns 50 query rows:
// scores (float4 over keys) -> softmax in registers -> PV via smem P row.
// Output written TRANSPOSED: g_ot[b][q][h*64+d] for coalesced stores.
__global__ void __launch_bounds__(256) k_attn() {
    extern __shared__ float sm[];
    float* Qs = sm;                       // [16][400]
    float* Ks = Qs + KDIM*NPIX;           // [16][400]
    float* Vs = Ks + KDIM*NPIX;           // [400][PADV]
    float* Ps = Vs + NPIX*PADV;           // [8][400]
    const int bh = blockIdx.x;
    const int b = bh >> 3, h = bh & 7;
    const int tid = threadIdx.x;

    const float* qb = g_qdw + ((size_t)b*128 + h*KDIM)*NPIX;
    const float* kb = g_qkv + ((size_t)b*HQ + 128 + h*KDIM)*NPIX;
    const float* vb = g_qkv + ((size_t)b*HQ + 256 + h*VDIM)*NPIX;

    for (int i = tid; i < KDIM*NPIX; i += 256) { Qs[i] = qb[i]; Ks[i] = kb[i]; }
    for (int i = tid; i < VDIM*NPIX; i += 256) {
        int d = i / NPIX, p = i - d*NPIX;
        Vs[p*PADV + d] = vb[i];
    }
    __syncthreads();

    const int w = tid >> 5, lane = tid & 31;
    float* Pw = Ps + w*NPIX;

    for (int q = w; q < NPIX; q += 8) {
        float qd[KDIM];
        #pragma unroll
        for (int d = 0; d < KDIM; d++) qd[d] = Qs[d*NPIX + q];
        const float* brow = g_bias + ((size_t)h*NPIX + q)*NPIX;

        float sreg[4][4];
        float mx = -1e30f;
        #pragma unroll
        for (int kk = 0; kk < 4; kk++) {
            const int key0 = kk*128 + lane*4;
            if (key0 < NPIX) {
                float s0 = 0.f, s1 = 0.f, s2 = 0.f, s3 = 0.f;
                #pragma unroll
                for (int d = 0; d < KDIM; d++) {
                    float4 kv = *(const float4*)&Ks[d*NPIX + key0];
                    float qv = qd[d];
                    s0 += qv*kv.x; s1 += qv*kv.y; s2 += qv*kv.z; s3 += qv*kv.w;
                }
                float4 bv = *(const float4*)&brow[key0];
                sreg[kk][0] = s0*0.25f + bv.x;
                sreg[kk][1] = s1*0.25f + bv.y;
                sreg[kk][2] = s2*0.25f + bv.z;
                sreg[kk][3] = s3*0.25f + bv.w;
                mx = fmaxf(mx, fmaxf(fmaxf(sreg[kk][0], sreg[kk][1]),
                                     fmaxf(sreg[kk][2], sreg[kk][3])));
            }
        }
        #pragma unroll
        for (int off = 16; off > 0; off >>= 1)
            mx = fmaxf(mx, __shfl_xor_sync(0xffffffffu, mx, off));

        float den = 0.f;
        #pragma unroll
        for (int kk = 0; kk < 4; kk++) {
            const int key0 = kk*128 + lane*4;
            if (key0 < NPIX) {
                float4 e;
                e.x = __expf(sreg[kk][0] - mx);
                e.y = __expf(sreg[kk][1] - mx);
                e.z = __expf(sreg[kk][2] - mx);
                e.w = __expf(sreg[kk][3] - mx);
                den += e.x + e.y + e.z + e.w;
                *(float4*)&Pw[key0] = e;
            }
        }
        #pragma unroll
        for (int off = 16; off > 0; off >>= 1)
            den += __shfl_xor_sync(0xffffffffu, den, off);
        const float inv = 1.f / den;
        __syncwarp();

        const int d0 = lane*2;
        float a0 = 0.f, a1 = 0.f;
        #pragma unroll 4
        for (int k4 = 0; k4 < NPIX/4; k4++) {
            float4 p4 = *(const float4*)&Pw[k4*4];
            const float* vr = &Vs[(k4*4)*PADV + d0];
            float2 v0 = *(const float2*)(vr);
            float2 v1 = *(const float2*)(vr + PADV);
            float2 v2 = *(const float2*)(vr + 2*PADV);
            float2 v3 = *(const float2*)(vr + 3*PADV);
            a0 += p4.x*v0.x; a1 += p4.x*v0.y;
            a0 += p4.y*v1.x; a1 += p4.y*v1.y;
            a0 += p4.z*v2.x; a1 += p4.z*v2.y;
            a0 += p4.w*v3.x; a1 += p4.w*v3.y;
        }
        float2 res; res.x = a0*inv; res.y = a1*inv;
        *(float2*)&g_ot[((size_t)b*NPIX + q)*DHD + h*VDIM + d0] = res;
        __syncwarp();
    }
}

// ---------------- launch ----------------
extern "C" void kernel_launch(void* const* d_in, const int* in_sizes, int n_in,
                              void* d_out, int out_size) {
    const float* x      = (const float*)d_in[0];
    const float* qkv_w  = (const float*)d_in[1];
    const float* qkv_s  = (const float*)d_in[2];
    const float* qkv_b  = (const float*)d_in[3];
    const float* dw_w   = (const float*)d_in[4];
    const float* dw_s   = (const float*)d_in[5];
    const float* dw_b   = (const float*)d_in[6];
    const float* proj_w = (const float*)d_in[7];
    const float* proj_s = (const float*)d_in[8];
    const float* proj_b = (const float*)d_in[9];
    const float* ab     = (const float*)d_in[10];
    const float* pw1_w  = (const float*)d_in[11];
    const float* pw1_s  = (const float*)d_in[12];
    const float* pw1_b  = (const float*)d_in[13];
    const float* pw2_w  = (const float*)d_in[14];
    const float* pw2_s  = (const float*)d_in[15];
    const float* pw2_b  = (const float*)d_in[16];
    const int*   idxs   = (const int*)d_in[17];

    float *p_qkv, *p_ot, *p_y1, *p_hb;
    cudaGetSymbolAddress((void**)&p_qkv, g_qkv);
    cudaGetSymbolAddress((void**)&p_ot,  g_ot);
    cudaGetSymbolAddress((void**)&p_y1,  g_y1);
    cudaGetSymbolAddress((void**)&p_hb,  g_hb);

    // bias pipeline (independent of the main path until attention)
    k_mtaps<<<1, 512>>>();
    k_bias1<<<(NHEAD*NPIX*SPIX + 255)/256, 256>>>(ab, idxs);
    k_bias2<<<(NHEAD*NPIX*NPIX + 255)/256, 256>>>();

    // qkv conv1x1
    k_gemm<<<dim3(7, HQ/64, NB), 256>>>(x, qkv_w, qkv_s, qkv_b, nullptr, p_qkv, HQ, EDIM, 0);
    // depthwise 3x3 on q
    k_dwconv<<<(NB*128*NPIX + 255)/256, 256>>>(dw_w, dw_s, dw_b);

    // fused attention
    const int smem = (KDIM*NPIX + KDIM*NPIX + NPIX*PADV + 8*NPIX) * 4; // 169600 B
    cudaFuncSetAttribute(k_attn, cudaFuncAttributeMaxDynamicSharedMemorySize, smem);
    k_attn<<<NB*NHEAD, 256, smem>>>();

    // proj (relu on input, transposed X, residual x) -> y1
    k_gemm<<<dim3(7, EDIM/64, NB), 256>>>(p_ot, proj_w, proj_s, proj_b, x, p_y1, EDIM, DHD, 1|4);
    // pw1 (relu on output) -> h
    k_gemm<<<dim3(7, DHD/64, NB), 256>>>(p_y1, pw1_w, pw1_s, pw1_b, nullptr, p_hb, DHD, EDIM, 2);
    // pw2 (residual y1) -> out
    k_gemm<<<dim3(7, EDIM/64, NB), 256>>>(p_hb, pw2_w, pw2_s, pw2_b, p_y1, (float*)d_out, EDIM, DHD, 0);
}